// round 17
// baseline (speedup 1.0000x reference)
#include <cuda_runtime.h>
#include <cuda_fp16.h>
#include <math.h>
#include <stdint.h>

// ---------------- problem constants ----------------
#define BATCH   64
#define SEQ     512
#define EDIM    512
#define HDIM    1024
#define VOCAB   32000
#define M0      (BATCH*SEQ)      // 32768 level-0 nodes
#define NSPLIT  4

// ---------------- device scratch (allocation-free rule) ----------------
__device__ half  g_EMBh[(size_t)VOCAB * EDIM];
__device__ half  g_HB0h[(size_t)M0 * HDIM];
__device__ half  g_HB0l[(size_t)M0 * HDIM];
__device__ half  g_HB1h[(size_t)(M0/2) * HDIM];
__device__ half  g_HB1l[(size_t)(M0/2) * HDIM];
__device__ half  g_RHh [(size_t)(M0/2) * 2 * HDIM];
__device__ half  g_W0h [(size_t)(2*HDIM) * EDIM];      // [2048][512]  K-major
__device__ half  g_UZRh[(size_t)(2*HDIM) * (2*HDIM)];  // [2048][2048]
__device__ half  g_UHh [(size_t)HDIM * (2*HDIM)];      // [1024][2048]
__device__ float g_PRE[(size_t)M0 * 2 * HDIM];
__device__ float g_Z  [(size_t)(M0/2) * HDIM];
__device__ float g_BL0[2*HDIM];
__device__ float g_BZR[2*HDIM];
__device__ float g_BH [HDIM];

// ================= helpers =================
__device__ __forceinline__ uint32_t smem_u32(const void* p) {
    uint32_t a;
    asm("{ .reg .u64 t; cvta.to.shared.u64 t, %1; cvt.u32.u64 %0, t; }" : "=r"(a) : "l"(p));
    return a;
}
__device__ __forceinline__ void split1(float v, half& h, half& l) {
    h = __float2half_rn(v);
    l = __float2half_rn(v - __half2float(h));
}
__device__ __forceinline__ float4 ld4h(const half* p) {
    uint2 u = *(const uint2*)p;
    __half2 a = *(__half2*)&u.x, b = *(__half2*)&u.y;
    float2 fa = __half22float2(a), fb = __half22float2(b);
    return make_float4(fa.x, fa.y, fb.x, fb.y);
}
__device__ __forceinline__ void st4split(half* ph, half* pl, float4 v) {
    half h0, l0, h1, l1, h2, l2, h3, l3;
    split1(v.x, h0, l0); split1(v.y, h1, l1);
    split1(v.z, h2, l2); split1(v.w, h3, l3);
    __half2 H0 = __halves2half2(h0, h1), H1 = __halves2half2(h2, h3);
    __half2 L0 = __halves2half2(l0, l1), L1 = __halves2half2(l2, l3);
    uint2 uh, ul;
    uh.x = *(uint32_t*)&H0; uh.y = *(uint32_t*)&H1;
    ul.x = *(uint32_t*)&L0; ul.y = *(uint32_t*)&L1;
    *(uint2*)ph = uh; *(uint2*)pl = ul;
}
__device__ __forceinline__ void st4hi(half* ph, float4 v) {
    __half2 a = __floats2half2_rn(v.x, v.y);
    __half2 b = __floats2half2_rn(v.z, v.w);
    uint2 u;
    u.x = *(uint32_t*)&a; u.y = *(uint32_t*)&b;
    *(uint2*)ph = u;
}

#define CP16(dst, src) asm volatile("cp.async.cg.shared.global [%0], [%1], 16;" :: "r"(dst), "l"(src))
#define CP_COMMIT()    asm volatile("cp.async.commit_group;" ::: "memory")
#define CP_WAIT(n)     asm volatile("cp.async.wait_group %0;" :: "n"(n) : "memory")

#define LDSM4(r0, r1, r2, r3, addr)                                              \
    asm volatile("ldmatrix.sync.aligned.m8n8.x4.shared.b16 {%0,%1,%2,%3}, [%4];" \
        : "=r"(r0), "=r"(r1), "=r"(r2), "=r"(r3) : "r"(addr))

#define MMA16816(d, a, b0, b1)                                                   \
    asm volatile("mma.sync.aligned.m16n8k16.row.col.f32.f16.f16.f32 "            \
        "{%0,%1,%2,%3}, {%4,%5,%6,%7}, {%8,%9}, {%0,%1,%2,%3};"                  \
        : "+f"((d)[0]), "+f"((d)[1]), "+f"((d)[2]), "+f"((d)[3])                  \
        : "r"((a)[0]), "r"((a)[1]), "r"((a)[2]), "r"((a)[3]), "r"(b0), "r"(b1))

__device__ __forceinline__ float sigmf(float x) { return 1.f / (1.f + expf(-x)); }

// ================= megapack =================
#define NB_EMB   16000
#define NB_W     512
#define NB_U     1024

struct PackArgs {
    const float *emb, *Wz, *Wh, *Uzl, *Url, *Uzr, *Urr, *Uhl, *Uhr;
    const float *bz, *bzl, *bzr, *br, *brl, *brr, *bh, *bhl, *bhr;
};

__device__ void do_transpose_hi(const float* __restrict__ src,
                                half* __restrict__ dh,
                                int R, int C, int dpitch, int blk, int tid)
{
    __shared__ float t[32][33];
    int gx = C / 32;
    int c0 = (blk % gx) * 32, r0 = (blk / gx) * 32;
    int x = tid & 31, y = tid >> 5;   // 32 x 8
    #pragma unroll
    for (int i = 0; i < 32; i += 8) {
        t[y + i][x] = src[(size_t)(r0 + y + i) * C + (c0 + x)];
    }
    __syncthreads();
    #pragma unroll
    for (int i = 0; i < 32; i += 8) {
        int c = c0 + y + i, r = r0 + x;
        dh[(size_t)c * dpitch + r] = __float2half_rn(t[x][y + i]);
    }
}

__global__ void __launch_bounds__(256) megapack_kernel(PackArgs a)
{
    const int tid = threadIdx.x;
    int blk = blockIdx.x;

    if (blk < NB_EMB) {
        int q = blk * 256 + tid;
        const int total4 = VOCAB * EDIM / 4;
        if (q < total4) {
            int idx = q * 4;
            float4 v = *(const float4*)(a.emb + idx);
            st4hi(g_EMBh + idx, v);
        }
        return;
    }
    blk -= NB_EMB;
    if (blk < 2 * NB_W) {
        if (blk < NB_W) do_transpose_hi(a.Wz, g_W0h, 512, 1024, 512, blk, tid);
        else            do_transpose_hi(a.Wh, g_W0h + (size_t)1024*512,
                                        512, 1024, 512, blk - NB_W, tid);
        return;
    }
    blk -= 2 * NB_W;
    if (blk < 4) {
        int i = blk * 256 + tid;
        float bzs = a.bz[i] + a.bzl[i] + a.bzr[i];
        float brs = a.br[i] + a.brl[i] + a.brr[i];
        float bhs = a.bh[i] + a.bhl[i] + a.bhr[i];
        g_BZR[i] = bzs; g_BZR[1024 + i] = brs;
        g_BH[i]  = bhs;
        g_BL0[i] = bzs; g_BL0[1024 + i] = bhs;
        return;
    }
    blk -= 4;
    {
        int which = blk / NB_U, b = blk % NB_U;
        switch (which) {
            case 0: do_transpose_hi(a.Uzl, g_UZRh, 1024, 1024, 2048, b, tid); break;
            case 1: do_transpose_hi(a.Url, g_UZRh + (size_t)1024*2048, 1024, 1024, 2048, b, tid); break;
            case 2: do_transpose_hi(a.Uzr, g_UZRh + 1024, 1024, 1024, 2048, b, tid); break;
            case 3: do_transpose_hi(a.Urr, g_UZRh + (size_t)1024*2048 + 1024, 1024, 1024, 2048, b, tid); break;
            case 4: do_transpose_hi(a.Uhl, g_UHh, 1024, 1024, 2048, b, tid); break;
            default: do_transpose_hi(a.Uhr, g_UHh + 1024, 1024, 1024, 2048, b, tid); break;
        }
    }
}

// seed PRE with broadcast bias (for split-K accumulation)
__global__ void seed_kernel(float* __restrict__ pre, const float* __restrict__ bias,
                            int total4, int Nmask)
{
    int q = blockIdx.x * blockDim.x + threadIdx.x;
    if (q >= total4) return;
    int idx = q * 4;
    int c = idx & Nmask;
    *(float4*)(pre + idx) = *(const float4*)(bias + c);
}

// ================= mma GEMM (1-term), 4 warps, warp tile (BMT/2)x64 =================
// C = Ah @ Bh^T (+bias). BMT in {64,128}. BN=128. TC=128 threads (2m x 2n warps).
// MF = BMT/32 m-fragments per warp (warp m-tile = BMT/2 rows).
#define BN 128
#define BK 32
#define PAD_B 80
#define NSTAGE 3

template<int BMT>
struct GemmCfg {
    static constexpr int TC    = 128;
    static constexpr int MF    = BMT / 32;            // m16 frags per warp (4 or 2)
    static constexpr int RT    = BMT + 128;           // rows per stage
    static constexpr int nseg  = RT * 4 / TC;         // 16B segs per thread (8 or 6)
    static constexpr int oBH   = BMT * PAD_B;
    static constexpr int stage = RT * PAD_B;          // 20480 / 15360
    static constexpr int smem  = NSTAGE * stage;      // 61440 / 46080
    static constexpr int occ   = (BMT == 128) ? 2 : 4;
};

template<int BMT, bool GATHER, bool SPLITK>
__global__ void __launch_bounds__(GemmCfg<BMT>::TC, GemmCfg<BMT>::occ)
gemm_mma_kernel(const half* __restrict__ Ah,
                const int* __restrict__ tok,
                const half* __restrict__ Bh,
                const float* __restrict__ bias,
                float* __restrict__ C, int M, int N, int K)
{
    using Cfg = GemmCfg<BMT>;
    constexpr int MF = Cfg::MF;
    extern __shared__ char smem[];
    const uint32_t sb = smem_u32(smem);
    const int tid  = threadIdx.x;
    const int lane = tid & 31;
    const int wid  = tid >> 5;
    const int warp_m = wid & 1;          // 2 m-warps of BMT/2 rows
    const int warp_n = wid >> 1;         // 2 n-warps of 64 cols
    const int bm = blockIdx.y * BMT, bn = blockIdx.x * BN;

    const int NTfull = K / BK;
    const int NT = SPLITK ? NTfull / NSPLIT : NTfull;
    const int gb = SPLITK ? (int)(blockIdx.z * NT) * 64 : 0;

    // ---- cp.async mapping ----
    const char* srcp[Cfg::nseg];
    uint32_t    dsto[Cfg::nseg];
    #pragma unroll
    for (int i = 0; i < Cfg::nseg; i++) {
        int s   = tid + Cfg::TC * i;
        int row = s >> 2;
        int sg  = (s & 3) * 16;
        dsto[i] = (uint32_t)(row * PAD_B + sg);
        if (row < BMT) {
            int gr = bm + row;
            size_t ar = GATHER ? (size_t)__ldg(&tok[gr]) : (size_t)gr;
            srcp[i] = (const char*)(Ah + ar * K) + sg + gb;
        } else {
            srcp[i] = (const char*)(Bh + (size_t)(bn + row - BMT) * K) + sg + gb;
        }
    }

    auto issue = [&](int kt) {
        if (kt < NT) {
            const uint32_t d = sb + (kt % NSTAGE) * Cfg::stage;
            const int g = kt * 64;
            #pragma unroll
            for (int i = 0; i < Cfg::nseg; i++) CP16(d + dsto[i], srcp[i] + g);
        }
        CP_COMMIT();
    };

    // ldmatrix lane addressing (A: warp m-tile = MF*16 rows; B: 64 cols per n-warp)
    const uint32_t a_lane_off = (uint32_t)((warp_m * (BMT / 2) + (lane & 15)) * PAD_B
                                           + ((lane >> 4) * 8) * 2);
    const uint32_t b_lane_off = (uint32_t)((warp_n * 64 + ((lane >> 4) << 3) + (lane & 7)) * PAD_B
                                           + (((lane >> 3) & 1) * 8) * 2);

    float acc[MF][8][4];
    #pragma unroll
    for (int mt = 0; mt < MF; mt++)
        #pragma unroll
        for (int t = 0; t < 8; t++)
            #pragma unroll
            for (int j = 0; j < 4; j++) acc[mt][t][j] = 0.f;

    issue(0);
    issue(1);

    for (int kt = 0; kt < NT; kt++) {
        CP_WAIT(1);
        __syncthreads();
        const uint32_t sbase = sb + (kt % NSTAGE) * Cfg::stage;

        #pragma unroll
        for (int ks = 0; ks < 2; ks++) {
            const uint32_t koff = ks * 32;
            uint32_t af[MF][4], bf[4][4];
            #pragma unroll
            for (int mt = 0; mt < MF; mt++) {
                uint32_t ad = sbase + a_lane_off + mt * (16 * PAD_B) + koff;
                LDSM4(af[mt][0], af[mt][1], af[mt][2], af[mt][3], ad);
            }
            #pragma unroll
            for (int ng = 0; ng < 4; ng++) {
                uint32_t bd = sbase + b_lane_off + ng * (16 * PAD_B) + koff;
                LDSM4(bf[ng][0], bf[ng][1], bf[ng][2], bf[ng][3], bd + Cfg::oBH);
            }
            if (ks == 0) issue(kt + 2);
            #pragma unroll
            for (int mt = 0; mt < MF; mt++)
                #pragma unroll
                for (int ng = 0; ng < 4; ng++)
                    #pragma unroll
                    for (int p = 0; p < 2; p++)
                        MMA16816(acc[mt][ng * 2 + p], af[mt], bf[ng][2 * p], bf[ng][2 * p + 1]);
        }
    }

    // ---- epilogue ----
    const int r0e = bm + warp_m * (BMT / 2) + (lane >> 2);
    const int c0e = bn + warp_n * 64 + (lane & 3) * 2;
    #pragma unroll
    for (int mt = 0; mt < MF; mt++) {
        const int row = r0e + mt * 16;
        #pragma unroll
        for (int t = 0; t < 8; t++) {
            const int col = c0e + t * 8;
            if (SPLITK) {
                atomicAdd(C + (size_t)row * N + col,           acc[mt][t][0]);
                atomicAdd(C + (size_t)row * N + col + 1,       acc[mt][t][1]);
                atomicAdd(C + (size_t)(row + 8) * N + col,     acc[mt][t][2]);
                atomicAdd(C + (size_t)(row + 8) * N + col + 1, acc[mt][t][3]);
            } else {
                const float b0 = bias[col], b1 = bias[col + 1];
                float2 v0 = make_float2(acc[mt][t][0] + b0, acc[mt][t][1] + b1);
                *(float2*)(C + (size_t)row * N + col) = v0;
                float2 v1 = make_float2(acc[mt][t][2] + b0, acc[mt][t][3] + b1);
                *(float2*)(C + (size_t)(row + 8) * N + col) = v1;
            }
        }
    }
}

// ================= elementwise epilogues =================
__global__ void e0_kernel(const float* __restrict__ pre,
                          half* __restrict__ hh, half* __restrict__ hl, int total4)
{
    int q = blockIdx.x * blockDim.x + threadIdx.x;
    if (q >= total4) return;
    int idx = q * 4;
    int m = idx >> 10, j = idx & 1023;
    size_t o = (size_t)m * 2048 + j;
    float4 zp = *(const float4*)(pre + o);
    float4 hp = *(const float4*)(pre + o + 1024);
    float4 r;
    r.x = (1.f - sigmf(zp.x)) * tanhf(hp.x);
    r.y = (1.f - sigmf(zp.y)) * tanhf(hp.y);
    r.z = (1.f - sigmf(zp.z)) * tanhf(hp.z);
    r.w = (1.f - sigmf(zp.w)) * tanhf(hp.w);
    st4split(hh + idx, hl + idx, r);
}

__global__ void e1_kernel(const float* __restrict__ pre,
                          const half* __restrict__ hph, const half* __restrict__ hpl,
                          float* __restrict__ zb,
                          half* __restrict__ rhh, int total4)
{
    int q = blockIdx.x * blockDim.x + threadIdx.x;
    if (q >= total4) return;
    int idx = q * 4;
    int m = idx >> 10, j = idx & 1023;
    size_t o = (size_t)m * 2048 + j;
    float4 zp = *(const float4*)(pre + o);
    float4 rp = *(const float4*)(pre + o + 1024);
    float4 Hh = ld4h(hph + o),        Lh = ld4h(hpl + o);
    float4 Hr = ld4h(hph + o + 1024), Lr = ld4h(hpl + o + 1024);
    float hlx = Hh.x + Lh.x, hly = Hh.y + Lh.y, hlz = Hh.z + Lh.z, hlw = Hh.w + Lh.w;
    float hrx = Hr.x + Lr.x, hry = Hr.y + Lr.y, hrz = Hr.z + Lr.z, hrw = Hr.w + Lr.w;
    float4 z;
    z.x = sigmf(zp.x); z.y = sigmf(zp.y); z.z = sigmf(zp.z); z.w = sigmf(zp.w);
    float rx = sigmf(rp.x), ry = sigmf(rp.y), rz = sigmf(rp.z), rw = sigmf(rp.w);
    *(float4*)(zb + idx) = z;
    st4hi(rhh + o,        make_float4(rx * hlx, ry * hly, rz * hlz, rw * hlw));
    st4hi(rhh + o + 1024, make_float4(rx * hrx, ry * hry, rz * hrz, rw * hrw));
}

template<bool FINAL>
__global__ void e2_kernel(const float* __restrict__ pre2, const float* __restrict__ zb,
                          const half* __restrict__ hph, const half* __restrict__ hpl,
                          half* __restrict__ hoh, half* __restrict__ hol,
                          float* __restrict__ outf, int total4)
{
    int q = blockIdx.x * blockDim.x + threadIdx.x;
    if (q >= total4) return;
    int idx = q * 4;
    int m = idx >> 10, j = idx & 1023;
    size_t o = (size_t)m * 2048 + j;
    float4 z  = *(const float4*)(zb + idx);
    float4 p  = *(const float4*)(pre2 + idx);
    float4 Hh = ld4h(hph + o),        Lh = ld4h(hpl + o);
    float4 Hr = ld4h(hph + o + 1024), Lr = ld4h(hpl + o + 1024);
    float4 r;
    r.x = z.x * ((Hh.x + Lh.x) + (Hr.x + Lr.x)) + (1.f - z.x) * tanhf(p.x);
    r.y = z.y * ((Hh.y + Lh.y) + (Hr.y + Lr.y)) + (1.f - z.y) * tanhf(p.y);
    r.z = z.z * ((Hh.z + Lh.z) + (Hr.z + Lr.z)) + (1.f - z.z) * tanhf(p.z);
    r.w = z.w * ((Hh.w + Lh.w) + (Hr.w + Lr.w)) + (1.f - z.w) * tanhf(p.w);
    if (FINAL) *(float4*)(outf + idx) = r;
    else       st4split(hoh + idx, hol + idx, r);
}

// ================= launch =================
extern "C" void kernel_launch(void* const* d_in, const int* in_sizes, int n_in,
                              void* d_out, int out_size)
{
    const int*   tokens = (const int*)  d_in[0];
    const float* emb    = (const float*)d_in[1];

    PackArgs pa;
    pa.emb = emb;
    pa.Wz  = (const float*)d_in[2];
    pa.bz  = (const float*)d_in[3];
    pa.Uzl = (const float*)d_in[4];
    pa.bzl = (const float*)d_in[5];
    pa.Uzr = (const float*)d_in[6];
    pa.bzr = (const float*)d_in[7];
    pa.br  = (const float*)d_in[9];
    pa.Url = (const float*)d_in[10];
    pa.brl = (const float*)d_in[11];
    pa.Urr = (const float*)d_in[12];
    pa.brr = (const float*)d_in[13];
    pa.Wh  = (const float*)d_in[14];
    pa.bh  = (const float*)d_in[15];
    pa.Uhl = (const float*)d_in[16];
    pa.bhl = (const float*)d_in[17];
    pa.Uhr = (const float*)d_in[18];
    pa.bhr = (const float*)d_in[19];

    half *EMBh, *HB0h, *HB0l, *HB1h, *HB1l, *RHh;
    half *W0h, *UZRh, *UHh;
    float *PRE, *ZB, *BL0, *BZR, *BH;
    cudaGetSymbolAddress((void**)&EMBh, g_EMBh);
    cudaGetSymbolAddress((void**)&HB0h, g_HB0h);
    cudaGetSymbolAddress((void**)&HB0l, g_HB0l);
    cudaGetSymbolAddress((void**)&HB1h, g_HB1h);
    cudaGetSymbolAddress((void**)&HB1l, g_HB1l);
    cudaGetSymbolAddress((void**)&RHh,  g_RHh);
    cudaGetSymbolAddress((void**)&W0h,  g_W0h);
    cudaGetSymbolAddress((void**)&UZRh, g_UZRh);
    cudaGetSymbolAddress((void**)&UHh,  g_UHh);
    cudaGetSymbolAddress((void**)&PRE,  g_PRE);
    cudaGetSymbolAddress((void**)&ZB,   g_Z);
    cudaGetSymbolAddress((void**)&BL0,  g_BL0);
    cudaGetSymbolAddress((void**)&BZR,  g_BZR);
    cudaGetSymbolAddress((void**)&BH,   g_BH);

    cudaFuncSetAttribute(gemm_mma_kernel<128, true,  false>,
                         cudaFuncAttributeMaxDynamicSharedMemorySize, GemmCfg<128>::smem);
    cudaFuncSetAttribute(gemm_mma_kernel<128, false, false>,
                         cudaFuncAttributeMaxDynamicSharedMemorySize, GemmCfg<128>::smem);
    cudaFuncSetAttribute(gemm_mma_kernel<64, false, true>,
                         cudaFuncAttributeMaxDynamicSharedMemorySize, GemmCfg<64>::smem);

    // ---- launch 0: megapack ----
    {
        int nblocks = NB_EMB + 2 * NB_W + 4 + 6 * NB_U;
        megapack_kernel<<<nblocks, 256>>>(pa);
    }

    // ---- launch 1: level-0 GEMM ; launch 2: e0 ----
    {
        dim3 grid(2 * HDIM / BN, M0 / 128);
        gemm_mma_kernel<128, true, false><<<grid, 128, GemmCfg<128>::smem>>>(
            EMBh, tokens, W0h, BL0, PRE, M0, 2 * HDIM, EDIM);
        int total4 = M0 * HDIM / 4;
        e0_kernel<<<(total4 + 255) / 256, 256>>>(PRE, HB0h, HB0l, total4);
    }

    // ---- tree levels (launch 3 = level-1 GEMM1, the ncu target) ----
    half* hph = HB0h; half* hpl = HB0l;
    int n = SEQ, lvl = 0;
    while (n > 1) {
        int Mn = BATCH * (n / 2);
        bool final = (n / 2 == 1);
        bool sk = (Mn <= 512);
        half* hoh = (lvl & 1) ? HB0h : HB1h;
        half* hol = (lvl & 1) ? HB0l : HB1l;
        int total4 = Mn * HDIM / 4;

        // GEMM1 (gates): h_hi @ UZRh + [bz|br]
        if (sk) {
            int t4 = Mn * 2 * HDIM / 4;
            seed_kernel<<<(t4 + 255) / 256, 256>>>(PRE, BZR, t4, 2 * HDIM - 1);
            dim3 grid(2 * HDIM / BN, Mn / 64, NSPLIT);
            gemm_mma_kernel<64, false, true><<<grid, 128, GemmCfg<64>::smem>>>(
                hph, nullptr, UZRh, BZR, PRE, Mn, 2 * HDIM, 2 * HDIM);
        } else {
            dim3 grid(2 * HDIM / BN, Mn / 128);
            gemm_mma_kernel<128, false, false><<<grid, 128, GemmCfg<128>::smem>>>(
                hph, nullptr, UZRh, BZR, PRE, Mn, 2 * HDIM, 2 * HDIM);
        }
        e1_kernel<<<(total4 + 255) / 256, 256>>>(PRE, hph, hpl, ZB, RHh, total4);
        // GEMM2 (h-tilde): rh_hi @ UHh + bh
        if (sk) {
            int t4 = Mn * HDIM / 4;
            seed_kernel<<<(t4 + 255) / 256, 256>>>(PRE, BH, t4, HDIM - 1);
            dim3 grid(HDIM / BN, Mn / 64, NSPLIT);
            gemm_mma_kernel<64, false, true><<<grid, 128, GemmCfg<64>::smem>>>(
                RHh, nullptr, UHh, BH, PRE, Mn, HDIM, 2 * HDIM);
        } else {
            dim3 grid(HDIM / BN, Mn / 128);
            gemm_mma_kernel<128, false, false><<<grid, 128, GemmCfg<128>::smem>>>(
                RHh, nullptr, UHh, BH, PRE, Mn, HDIM, 2 * HDIM);
        }
        if (final)
            e2_kernel<true><<<(total4 + 255) / 256, 256>>>(PRE, ZB, hph, hpl, nullptr, nullptr,
                                                           (float*)d_out, total4);
        else
            e2_kernel<false><<<(total4 + 255) / 256, 256>>>(PRE, ZB, hph, hpl, hoh, hol,
                                                            nullptr, total4);

        hph = hoh; hpl = hol;
        n /= 2;
        lvl++;
    }
    (void)in_sizes; (void)n_in; (void)out_size;
}